// round 13
// baseline (speedup 1.0000x reference)
#include <cuda_runtime.h>

#define GS 32
#define G3 32768
#define BATCH 256
#define NPTS 4096
#define CHUNKS 4
#define PTS_PER_BLK (NPTS / CHUNKS)            // 1024
#define THREADS 128
#define PTS_PER_THREAD (PTS_PER_BLK / THREADS) // 8
#define NWARPS (THREADS / 32)                  // 4
#define NWORDS (G3 / 32)                       // 1024
#define TOTAL_WORDS (BATCH * NWORDS)           // 262144
#define WPW 8                                  // words per warp in build kernel

__device__ unsigned g_bitmap[TOTAL_WORDS];     // 1MB scratch

// Fully parallel bitmap build: each warp packs WPW words (independent LDG batch),
// plus block 0 zeroes the output accumulators.
__global__ __launch_bounds__(256) void build_bitmap_kernel(
    const float* __restrict__ voxel, float* __restrict__ out, int out_size)
{
    if (blockIdx.x == 0 && threadIdx.x < out_size) out[threadIdx.x] = 0.f;

    int lid = threadIdx.x & 31;
    int warp = (blockIdx.x * blockDim.x + threadIdx.x) >> 5;
    int w0 = warp * WPW;
    float v[WPW];
    #pragma unroll
    for (int j = 0; j < WPW; j++)                 // WPW independent coalesced loads
        v[j] = voxel[(size_t)(w0 + j) * 32 + lid];
    #pragma unroll
    for (int j = 0; j < WPW; j++) {
        unsigned bits = __ballot_sync(0xffffffffu, v[j] > 0.5f);
        if (lid == 0) g_bitmap[w0 + j] = bits;
    }
}

// Same structure as the proven best (R6), but 128-thread blocks so the whole
// grid (1024 CTAs) is resident in ONE wave (8 CTAs/SM) -> no tail/imbalance.
__global__ __launch_bounds__(THREADS, 8) void symloss_kernel(
    const float* __restrict__ points,
    const float* __restrict__ cp,
    const float* __restrict__ plane,
    const float* __restrict__ quat,
    float* __restrict__ out)
{
    __shared__ float tf[6][12];   // per-transform affine: m[9], t[3]
    int tid = threadIdx.x;

    // --- 6 affine transforms (p' = M p + t) ---
    if (tid < 6) {
        float m[9], t[3];
        if (tid < 3) {
            const float* p = plane + tid * 4;
            float nx = p[0], ny = p[1], nz = p[2], d = p[3];
            float k = 2.0f / (nx*nx + ny*ny + nz*nz);
            m[0] = 1.f - k*nx*nx; m[1] = -k*nx*ny;       m[2] = -k*nx*nz;
            m[3] = -k*ny*nx;      m[4] = 1.f - k*ny*ny;  m[5] = -k*ny*nz;
            m[6] = -k*nz*nx;      m[7] = -k*nz*ny;       m[8] = 1.f - k*nz*nz;
            t[0] = -k*d*nx; t[1] = -k*d*ny; t[2] = -k*d*nz;
        } else {
            const float* q = quat + (tid - 3) * 4;
            float qn = rsqrtf(q[0]*q[0] + q[1]*q[1] + q[2]*q[2] + q[3]*q[3]);
            float w = q[0]*qn, ux = q[1]*qn, uy = q[2]*qn, uz = q[3]*qn;
            m[0] = 1.f - 2.f*(uy*uy + uz*uz); m[1] = 2.f*(ux*uy - w*uz);        m[2] = 2.f*(ux*uz + w*uy);
            m[3] = 2.f*(ux*uy + w*uz);        m[4] = 1.f - 2.f*(ux*ux + uz*uz); m[5] = 2.f*(uy*uz - w*ux);
            m[6] = 2.f*(ux*uz - w*uy);        m[7] = 2.f*(uy*uz + w*ux);        m[8] = 1.f - 2.f*(ux*ux + uy*uy);
            t[0] = t[1] = t[2] = 0.f;
        }
        #pragma unroll
        for (int j = 0; j < 9; j++) tf[tid][j] = m[j];
        #pragma unroll
        for (int j = 0; j < 3; j++) tf[tid][9 + j] = t[j];
    }
    __syncthreads();

    int blk = blockIdx.x;
    int b = blk / CHUNKS;
    int chunk = blk % CHUNKS;
    const float* pbase = points + ((size_t)b * NPTS + (size_t)chunk * PTS_PER_BLK) * 3;
    const float* cpb   = cp + (size_t)b * G3 * 3;
    const unsigned* bmp = g_bitmap + b * NWORDS;   // 4KB, L1-resident

    const float GMIN = -0.484375f;  // -0.5 + 0.5/32

    float accP = 0.f, accR = 0.f;

    #pragma unroll
    for (int s = 0; s < 6; s++) {
        float m0 = tf[s][0], m1 = tf[s][1], m2 = tf[s][2];
        float m3 = tf[s][3], m4 = tf[s][4], m5 = tf[s][5];
        float m6 = tf[s][6], m7 = tf[s][7], m8 = tf[s][8];
        float t0 = tf[s][9], t1 = tf[s][10], t2 = tf[s][11];
        float acc = 0.f;
        // keep the proven 4-point batching pattern; loop runs twice
        #pragma unroll 4
        for (int it = 0; it < PTS_PER_THREAD; it++) {
            int n = tid + it * THREADS;
            float x = pbase[n*3 + 0];
            float y = pbase[n*3 + 1];
            float z = pbase[n*3 + 2];
            float px = fmaf(m0, x, fmaf(m1, y, fmaf(m2, z, t0)));
            float py = fmaf(m3, x, fmaf(m4, y, fmaf(m5, z, t1)));
            float pz = fmaf(m6, x, fmaf(m7, y, fmaf(m8, z, t2)));
            float ix = rintf(fminf(fmaxf((px - GMIN) * 32.f, 0.f), 31.f));
            float iy = rintf(fminf(fmaxf((py - GMIN) * 32.f, 0.f), 31.f));
            float iz = rintf(fminf(fmaxf((pz - GMIN) * 32.f, 0.f), 31.f));
            int idx = (int)ix * 1024 + (int)iy * 32 + (int)iz;

            // All loads address-independent -> full MLP.
            unsigned word = __ldg(bmp + (idx >> 5));

            // cp row [3*idx, 3*idx+3) via two 8B-aligned LDG.64 covering [f, f+4)
            int f = (idx * 3) & ~1;
            float2 v0 = __ldg((const float2*)(cpb + f));
            float2 v1 = __ldg((const float2*)(cpb + f + 2));
            bool odd = (idx & 1) != 0;
            float cx = odd ? v0.y : v0.x;
            float cy = odd ? v1.x : v0.y;
            float cz = odd ? v1.y : v1.x;

            float mk = ((word >> (idx & 31)) & 1u) ? 0.0f : 1.0f;
            float dx = (px - cx) * mk;
            float dy = (py - cy) * mk;
            float dz = (pz - cz) * mk;
            acc = fmaf(dx, dx, fmaf(dy, dy, fmaf(dz, dz, acc)));
        }
        if (s < 3) accP += acc; else accR += acc;
    }

    // --- block reduction ---
    #pragma unroll
    for (int off = 16; off > 0; off >>= 1) {
        accP += __shfl_down_sync(0xffffffffu, accP, off);
        accR += __shfl_down_sync(0xffffffffu, accR, off);
    }
    __shared__ float redP[NWARPS], redR[NWARPS];
    int wid = tid >> 5, lid = tid & 31;
    if (lid == 0) { redP[wid] = accP; redR[wid] = accR; }
    __syncthreads();
    if (wid == 0) {
        accP = (lid < NWARPS) ? redP[lid] : 0.f;
        accR = (lid < NWARPS) ? redR[lid] : 0.f;
        #pragma unroll
        for (int off = 2; off > 0; off >>= 1) {
            accP += __shfl_down_sync(0xffffffffu, accP, off);
            accR += __shfl_down_sync(0xffffffffu, accR, off);
        }
        if (lid == 0) {
            atomicAdd(out + 0, accP * (1.0f / BATCH));
            atomicAdd(out + 1, accR * (1.0f / BATCH));
        }
    }
}

extern "C" void kernel_launch(void* const* d_in, const int* in_sizes, int n_in,
                              void* d_out, int out_size) {
    const float* points = (const float*)d_in[0];
    const float* cp     = (const float*)d_in[1];
    const float* voxel  = (const float*)d_in[2];
    const float* plane  = (const float*)d_in[3];
    const float* quat   = (const float*)d_in[4];
    float* out = (float*)d_out;

    // 262144 words / (8 warps * WPW words) = 4096 blocks
    build_bitmap_kernel<<<TOTAL_WORDS / (8 * WPW), 256>>>(voxel, out, out_size);
    symloss_kernel<<<BATCH * CHUNKS, THREADS>>>(points, cp, plane, quat, out);
}

// round 14
// speedup vs baseline: 1.0111x; 1.0111x over previous
#include <cuda_runtime.h>

#define GS 32
#define G3 32768
#define BATCH 256
#define NPTS 4096
#define CHUNKS 4
#define PTS_PER_BLK (NPTS / CHUNKS)            // 1024
#define THREADS 256
#define PTS_PER_THREAD (PTS_PER_BLK / THREADS) // 4
#define NWARPS (THREADS / 32)                  // 8
#define NWORDS (G3 / 32)                       // 1024
#define TOTAL_WORDS (BATCH * NWORDS)           // 262144

__device__ unsigned g_bitmap[TOTAL_WORDS];     // 1MB scratch

// Ballot-free bitmap build: each thread packs 8 voxel floats -> 1 byte of the
// word bitmap. Little-endian byte view => bit (idx&31) of word == bit (idx&7)
// of byte ((idx>>3)): semantics identical to the ballot build.
// 2x coalesced float4 loads + 1 coalesced byte store; block 0 zeroes out[].
__global__ __launch_bounds__(256) void build_bitmap_kernel(
    const float* __restrict__ voxel, float* __restrict__ out, int out_size)
{
    if (blockIdx.x == 0 && threadIdx.x < out_size) out[threadIdx.x] = 0.f;

    int g = blockIdx.x * blockDim.x + threadIdx.x;      // byte index
    const float4* v4 = (const float4*)voxel;
    float4 a = __ldg(v4 + 2 * (size_t)g);
    float4 c = __ldg(v4 + 2 * (size_t)g + 1);
    unsigned byte =
        (a.x > 0.5f ? 1u : 0u)  | (a.y > 0.5f ? 2u : 0u)  |
        (a.z > 0.5f ? 4u : 0u)  | (a.w > 0.5f ? 8u : 0u)  |
        (c.x > 0.5f ? 16u : 0u) | (c.y > 0.5f ? 32u : 0u) |
        (c.z > 0.5f ? 64u : 0u) | (c.w > 0.5f ? 128u : 0u);
    ((unsigned char*)g_bitmap)[g] = (unsigned char)byte;
}

// ====== symloss kernel: byte-for-byte the proven R6/R10 best (44.0us) ======
__global__ __launch_bounds__(THREADS) void symloss_kernel(
    const float* __restrict__ points,
    const float* __restrict__ cp,
    const float* __restrict__ plane,
    const float* __restrict__ quat,
    float* __restrict__ out)
{
    __shared__ float tf[6][12];   // per-transform affine: m[9], t[3]
    int tid = threadIdx.x;

    // --- 6 affine transforms (p' = M p + t) ---
    if (tid < 6) {
        float m[9], t[3];
        if (tid < 3) {
            const float* p = plane + tid * 4;
            float nx = p[0], ny = p[1], nz = p[2], d = p[3];
            float k = 2.0f / (nx*nx + ny*ny + nz*nz);
            m[0] = 1.f - k*nx*nx; m[1] = -k*nx*ny;       m[2] = -k*nx*nz;
            m[3] = -k*ny*nx;      m[4] = 1.f - k*ny*ny;  m[5] = -k*ny*nz;
            m[6] = -k*nz*nx;      m[7] = -k*nz*ny;       m[8] = 1.f - k*nz*nz;
            t[0] = -k*d*nx; t[1] = -k*d*ny; t[2] = -k*d*nz;
        } else {
            const float* q = quat + (tid - 3) * 4;
            float qn = rsqrtf(q[0]*q[0] + q[1]*q[1] + q[2]*q[2] + q[3]*q[3]);
            float w = q[0]*qn, ux = q[1]*qn, uy = q[2]*qn, uz = q[3]*qn;
            m[0] = 1.f - 2.f*(uy*uy + uz*uz); m[1] = 2.f*(ux*uy - w*uz);        m[2] = 2.f*(ux*uz + w*uy);
            m[3] = 2.f*(ux*uy + w*uz);        m[4] = 1.f - 2.f*(ux*ux + uz*uz); m[5] = 2.f*(uy*uz - w*ux);
            m[6] = 2.f*(ux*uz - w*uy);        m[7] = 2.f*(uy*uz + w*ux);        m[8] = 1.f - 2.f*(ux*ux + uy*uy);
            t[0] = t[1] = t[2] = 0.f;
        }
        #pragma unroll
        for (int j = 0; j < 9; j++) tf[tid][j] = m[j];
        #pragma unroll
        for (int j = 0; j < 3; j++) tf[tid][9 + j] = t[j];
    }
    __syncthreads();

    int blk = blockIdx.x;
    int b = blk / CHUNKS;
    int chunk = blk % CHUNKS;
    const float* pbase = points + ((size_t)b * NPTS + (size_t)chunk * PTS_PER_BLK) * 3;
    const float* cpb   = cp + (size_t)b * G3 * 3;
    const unsigned* bmp = g_bitmap + b * NWORDS;   // 4KB, L1-resident

    const float GMIN = -0.484375f;  // -0.5 + 0.5/32

    float accP = 0.f, accR = 0.f;

    #pragma unroll
    for (int s = 0; s < 6; s++) {
        float m0 = tf[s][0], m1 = tf[s][1], m2 = tf[s][2];
        float m3 = tf[s][3], m4 = tf[s][4], m5 = tf[s][5];
        float m6 = tf[s][6], m7 = tf[s][7], m8 = tf[s][8];
        float t0 = tf[s][9], t1 = tf[s][10], t2 = tf[s][11];
        float acc = 0.f;
        #pragma unroll
        for (int it = 0; it < PTS_PER_THREAD; it++) {
            int n = tid + it * THREADS;
            float x = pbase[n*3 + 0];
            float y = pbase[n*3 + 1];
            float z = pbase[n*3 + 2];
            float px = fmaf(m0, x, fmaf(m1, y, fmaf(m2, z, t0)));
            float py = fmaf(m3, x, fmaf(m4, y, fmaf(m5, z, t1)));
            float pz = fmaf(m6, x, fmaf(m7, y, fmaf(m8, z, t2)));
            float ix = rintf(fminf(fmaxf((px - GMIN) * 32.f, 0.f), 31.f));
            float iy = rintf(fminf(fmaxf((py - GMIN) * 32.f, 0.f), 31.f));
            float iz = rintf(fminf(fmaxf((pz - GMIN) * 32.f, 0.f), 31.f));
            int idx = (int)ix * 1024 + (int)iy * 32 + (int)iz;

            // All loads address-independent -> full MLP.
            unsigned word = __ldg(bmp + (idx >> 5));

            // cp row [3*idx, 3*idx+3) via two 8B-aligned LDG.64 covering [f, f+4)
            int f = (idx * 3) & ~1;
            float2 v0 = __ldg((const float2*)(cpb + f));
            float2 v1 = __ldg((const float2*)(cpb + f + 2));
            bool odd = (idx & 1) != 0;
            float cx = odd ? v0.y : v0.x;
            float cy = odd ? v1.x : v0.y;
            float cz = odd ? v1.y : v1.x;

            float mk = ((word >> (idx & 31)) & 1u) ? 0.0f : 1.0f;
            float dx = (px - cx) * mk;
            float dy = (py - cy) * mk;
            float dz = (pz - cz) * mk;
            acc = fmaf(dx, dx, fmaf(dy, dy, fmaf(dz, dz, acc)));
        }
        if (s < 3) accP += acc; else accR += acc;
    }

    // --- block reduction ---
    #pragma unroll
    for (int off = 16; off > 0; off >>= 1) {
        accP += __shfl_down_sync(0xffffffffu, accP, off);
        accR += __shfl_down_sync(0xffffffffu, accR, off);
    }
    __shared__ float redP[NWARPS], redR[NWARPS];
    int wid = tid >> 5, lid = tid & 31;
    if (lid == 0) { redP[wid] = accP; redR[wid] = accR; }
    __syncthreads();
    if (wid == 0) {
        accP = (lid < NWARPS) ? redP[lid] : 0.f;
        accR = (lid < NWARPS) ? redR[lid] : 0.f;
        #pragma unroll
        for (int off = 4; off > 0; off >>= 1) {
            accP += __shfl_down_sync(0xffffffffu, accP, off);
            accR += __shfl_down_sync(0xffffffffu, accR, off);
        }
        if (lid == 0) {
            atomicAdd(out + 0, accP * (1.0f / BATCH));
            atomicAdd(out + 1, accR * (1.0f / BATCH));
        }
    }
}

extern "C" void kernel_launch(void* const* d_in, const int* in_sizes, int n_in,
                              void* d_out, int out_size) {
    const float* points = (const float*)d_in[0];
    const float* cp     = (const float*)d_in[1];
    const float* voxel  = (const float*)d_in[2];
    const float* plane  = (const float*)d_in[3];
    const float* quat   = (const float*)d_in[4];
    float* out = (float*)d_out;

    // 1MB of bitmap bytes, 1 byte/thread: 4096 blocks x 256 threads
    build_bitmap_kernel<<<(TOTAL_WORDS * 4) / 256, 256>>>(voxel, out, out_size);
    symloss_kernel<<<BATCH * CHUNKS, THREADS>>>(points, cp, plane, quat, out);
}